// round 6
// baseline (speedup 1.0000x reference)
#include <cuda_runtime.h>
#include <cuda_bf16.h>
#include <cstdint>

// Problem constants
constexpr int Bn = 8, Sn = 2048, Dn = 2048, Rn = 512, En = 8;
constexpr int Mn = Bn * Sn;  // 16384 tokens

// Scratch (device globals: allocation-free rule)
__device__ __align__(1024) __nv_bfloat16 g_xb[(size_t)Mn * Dn];   // 64 MB LN'd acts
__device__ __align__(1024) __nv_bfloat16 g_w1b[(size_t)Dn * Rn];  // 2 MB w1 bf16 [D,R]
__device__ float g_H[Bn * Rn];   // per-batch sum of GELU outputs
__device__ float g_T[Bn * Rn];   // per-batch T = H@w2 + S*b2 (seeded with S*b2)

// ---------------------------------------------------------------------------
__device__ __forceinline__ void cp_async16(uint32_t smem_dst, const void* gmem_src) {
    asm volatile("cp.async.cg.shared.global [%0], [%1], 16;\n" :: "r"(smem_dst), "l"(gmem_src));
}
#define CP_COMMIT() asm volatile("cp.async.commit_group;\n" ::)

__device__ __forceinline__ float gelu_exact(float x) {
    return 0.5f * x * (1.f + erff(x * 0.7071067811865475f));
}

__device__ __forceinline__ void mma16816(float* c, const uint32_t* a, uint32_t b0, uint32_t b1) {
    asm volatile(
        "mma.sync.aligned.m16n8k16.row.col.f32.bf16.bf16.f32 "
        "{%0,%1,%2,%3}, {%4,%5,%6,%7}, {%8,%9}, {%0,%1,%2,%3};"
        : "+f"(c[0]), "+f"(c[1]), "+f"(c[2]), "+f"(c[3])
        : "r"(a[0]), "r"(a[1]), "r"(a[2]), "r"(a[3]), "r"(b0), "r"(b1));
}

// ---------------------------------------------------------------------------
// Kernel 1: cast w1 -> bf16, zero H, seed T with S*b2
// ---------------------------------------------------------------------------
__global__ void prep_kernel(const float* __restrict__ w1, const float* __restrict__ b2) {
    int idx = blockIdx.x * blockDim.x + threadIdx.x;
    if (idx < Dn * Rn) g_w1b[idx] = __float2bfloat16(w1[idx]);
    if (idx < Bn * Rn) {
        g_H[idx] = 0.f;
        g_T[idx] = (float)Sn * b2[idx & (Rn - 1)];
    }
}

// ---------------------------------------------------------------------------
// Kernel 2: LayerNorm per token, write bf16
// ---------------------------------------------------------------------------
__global__ void ln_kernel(const float* __restrict__ hs,
                          const float* __restrict__ gamma,
                          const float* __restrict__ beta) {
    const int token = blockIdx.x;
    const int t = threadIdx.x;
    const float4* row = reinterpret_cast<const float4*>(hs + (size_t)token * Dn);
    float4 v0 = row[t];
    float4 v1 = row[t + 256];
    float s  = v0.x + v0.y + v0.z + v0.w + v1.x + v1.y + v1.z + v1.w;
    float ss = v0.x*v0.x + v0.y*v0.y + v0.z*v0.z + v0.w*v0.w
             + v1.x*v1.x + v1.y*v1.y + v1.z*v1.z + v1.w*v1.w;
    #pragma unroll
    for (int o = 16; o; o >>= 1) {
        s  += __shfl_xor_sync(0xFFFFFFFFu, s,  o);
        ss += __shfl_xor_sync(0xFFFFFFFFu, ss, o);
    }
    __shared__ float rs[8], rss[8];
    const int w = t >> 5, l = t & 31;
    if (l == 0) { rs[w] = s; rss[w] = ss; }
    __syncthreads();
    if (t < 32) {
        float a = (t < 8) ? rs[t] : 0.f;
        float c = (t < 8) ? rss[t] : 0.f;
        #pragma unroll
        for (int o = 4; o; o >>= 1) {
            a += __shfl_xor_sync(0xFFFFFFFFu, a, o);
            c += __shfl_xor_sync(0xFFFFFFFFu, c, o);
        }
        if (t == 0) { rs[0] = a; rss[0] = c; }
    }
    __syncthreads();
    const float mu   = rs[0] * (1.f / Dn);
    const float var  = rss[0] * (1.f / Dn) - mu * mu;
    const float rstd = rsqrtf(var + 1e-5f);

    const float4* g4 = reinterpret_cast<const float4*>(gamma);
    const float4* b4 = reinterpret_cast<const float4*>(beta);
    __nv_bfloat162* out2 = reinterpret_cast<__nv_bfloat162*>(g_xb + (size_t)token * Dn);
    {
        float4 g = g4[t], bb = b4[t];
        out2[2*t]   = __floats2bfloat162_rn((v0.x-mu)*rstd*g.x+bb.x, (v0.y-mu)*rstd*g.y+bb.y);
        out2[2*t+1] = __floats2bfloat162_rn((v0.z-mu)*rstd*g.z+bb.z, (v0.w-mu)*rstd*g.w+bb.w);
    }
    {
        int t2 = t + 256;
        float4 g = g4[t2], bb = b4[t2];
        out2[2*t2]   = __floats2bfloat162_rn((v1.x-mu)*rstd*g.x+bb.x, (v1.y-mu)*rstd*g.y+bb.y);
        out2[2*t2+1] = __floats2bfloat162_rn((v1.z-mu)*rstd*g.z+bb.z, (v1.w-mu)*rstd*g.w+bb.w);
    }
}

// ---------------------------------------------------------------------------
// nop: shifts the ncu capture slot onto the GEMM
// ---------------------------------------------------------------------------
__global__ void nop_kernel() {}

// ---------------------------------------------------------------------------
// Kernel 3: GEMM (xb @ w1b) + bias + exact GELU + per-batch column reduction
//   BM=128 BN=128 BK=32, 256 threads (8 warps, warp tile 32x64), 4-stage pipe
//   k-loop unrolled by the stage period so stage offsets are immediates
// ---------------------------------------------------------------------------
constexpr int BM = 128, BN = 128, BK = 32;
constexpr int STAGES = 4;
constexpr int ASTR = 40;    // bf16 elems per A row (pad 32->40)
constexpr int BSTR = 136;   // bf16 elems per B row (pad 128->136)
constexpr int A_BUF = BM * ASTR;   // 5120 elems
constexpr int B_BUF = BK * BSTR;   // 4352 elems
constexpr int SMEM_BYTES = STAGES * (A_BUF + B_BUF) * 2;  // 75776

__global__ __launch_bounds__(256) void gemm_kernel(const float* __restrict__ b1) {
    extern __shared__ __align__(1024) unsigned char smem[];
    __nv_bfloat16* sA = reinterpret_cast<__nv_bfloat16*>(smem);
    __nv_bfloat16* sB = sA + STAGES * A_BUF;
    __shared__ float part[4][BN];

    const int tid = threadIdx.x;
    const int bn = blockIdx.x;   // 0..3
    const int bm = blockIdx.y;   // 0..127
    const int warp = tid >> 5, lane = tid & 31;
    const int wm = warp >> 1, wn = warp & 1;

    const uint32_t asBase = (uint32_t)__cvta_generic_to_shared(sA);
    const uint32_t bsBase = (uint32_t)__cvta_generic_to_shared(sB);

    float acc[2][8][4];
    #pragma unroll
    for (int i = 0; i < 2; ++i)
        #pragma unroll
        for (int j = 0; j < 8; ++j)
            #pragma unroll
            for (int k = 0; k < 4; ++k) acc[i][j][k] = 0.f;

    // gmem load indexing
    const int a_r = tid >> 2, a_c = (tid & 3) * 8;     // A: 64 rows/pass, 2 passes
    const int b_r = tid >> 4, b_c = (tid & 15) * 8;    // B: 16 rows/pass, 2 passes
    const __nv_bfloat16* gA = g_xb + (size_t)(bm * BM) * Dn;
    const __nv_bfloat16* gB = g_w1b + (size_t)bn * BN;

    // per-thread smem targets (stage 0); stage adds immediate later
    const uint32_t adst0 = asBase + 2u * (uint32_t)(a_r * ASTR + a_c);
    const uint32_t adst1 = asBase + 2u * (uint32_t)((a_r + 64) * ASTR + a_c);
    const uint32_t bdst0 = bsBase + 2u * (uint32_t)(b_r * BSTR + b_c);
    const uint32_t bdst1 = bsBase + 2u * (uint32_t)((b_r + 16) * BSTR + b_c);

    // per-warp ldmatrix base addresses (stage 0, ks 0)
    uint32_t abase[2], bbase[4];
    #pragma unroll
    for (int im = 0; im < 2; ++im)
        abase[im] = asBase + 2u * (uint32_t)((wm * 32 + im * 16 + (lane & 15)) * ASTR
                                             + ((lane >> 4) << 3));
    #pragma unroll
    for (int jq = 0; jq < 4; ++jq)
        bbase[jq] = bsBase + 2u * (uint32_t)((lane & 15) * BSTR
                                             + wn * 64 + jq * 16 + ((lane >> 4) << 3));

    constexpr int KT = Dn / BK;  // 64

    auto load_stage = [&](int kt, int stg) {
        const int k0 = kt * BK;
        const uint32_t ao = 2u * (uint32_t)(stg * A_BUF);
        const uint32_t bo = 2u * (uint32_t)(stg * B_BUF);
        cp_async16(adst0 + ao, gA + (size_t)a_r * Dn + k0 + a_c);
        cp_async16(adst1 + ao, gA + (size_t)(a_r + 64) * Dn + k0 + a_c);
        cp_async16(bdst0 + bo, gB + (size_t)(k0 + b_r) * Rn + b_c);
        cp_async16(bdst1 + bo, gB + (size_t)(k0 + b_r + 16) * Rn + b_c);
    };

    // prologue: stages 0..2 in flight
    load_stage(0, 0); CP_COMMIT();
    load_stage(1, 1); CP_COMMIT();
    load_stage(2, 2); CP_COMMIT();

    for (int kt0 = 0; kt0 < KT; kt0 += STAGES) {
        #pragma unroll
        for (int s = 0; s < STAGES; ++s) {
            const int kt = kt0 + s;
            if (kt + 3 < KT) load_stage(kt + 3, (s + 3) & 3);
            CP_COMMIT();
            asm volatile("cp.async.wait_group 3;\n" ::);
            __syncthreads();

            #pragma unroll
            for (int ks = 0; ks < BK; ks += 16) {
                const uint32_t aoff = 2u * (uint32_t)(s * A_BUF + ks);
                const uint32_t boff = 2u * (uint32_t)(s * B_BUF + ks * BSTR);
                uint32_t ra[2][4], rb[4][4];
                #pragma unroll
                for (int im = 0; im < 2; ++im)
                    asm volatile("ldmatrix.sync.aligned.m8n8.x4.shared.b16 {%0,%1,%2,%3}, [%4];"
                        : "=r"(ra[im][0]), "=r"(ra[im][1]), "=r"(ra[im][2]), "=r"(ra[im][3])
                        : "r"(abase[im] + aoff));
                #pragma unroll
                for (int jq = 0; jq < 4; ++jq)
                    asm volatile("ldmatrix.sync.aligned.m8n8.x4.trans.shared.b16 {%0,%1,%2,%3}, [%4];"
                        : "=r"(rb[jq][0]), "=r"(rb[jq][1]), "=r"(rb[jq][2]), "=r"(rb[jq][3])
                        : "r"(bbase[jq] + boff));
                #pragma unroll
                for (int im = 0; im < 2; ++im)
                    #pragma unroll
                    for (int j = 0; j < 8; ++j)
                        mma16816(acc[im][j], ra[im],
                                 rb[j >> 1][(j & 1) * 2], rb[j >> 1][(j & 1) * 2 + 1]);
            }
            __syncthreads();
        }
    }

    // Epilogue: bias + GELU + warp-level column sums
    const int tq = lane & 3;
    const int batch = bm >> 4;
    #pragma unroll
    for (int j = 0; j < 8; ++j) {
        const int gc = bn * BN + wn * 64 + j * 8 + tq * 2;
        const float bi0 = __ldg(b1 + gc), bi1 = __ldg(b1 + gc + 1);
        float s0 = 0.f, s1 = 0.f;
        #pragma unroll
        for (int im = 0; im < 2; ++im) {
            s0 += gelu_exact(acc[im][j][0] + bi0) + gelu_exact(acc[im][j][2] + bi0);
            s1 += gelu_exact(acc[im][j][1] + bi1) + gelu_exact(acc[im][j][3] + bi1);
        }
        #pragma unroll
        for (int o = 4; o <= 16; o <<= 1) {
            s0 += __shfl_xor_sync(0xFFFFFFFFu, s0, o);
            s1 += __shfl_xor_sync(0xFFFFFFFFu, s1, o);
        }
        if (lane < 4) {
            part[wm][wn * 64 + j * 8 + lane * 2]     = s0;
            part[wm][wn * 64 + j * 8 + lane * 2 + 1] = s1;
        }
    }
    __syncthreads();
    if (tid < BN) {
        float s = part[0][tid] + part[1][tid] + part[2][tid] + part[3][tid];
        atomicAdd(&g_H[batch * Rn + bn * BN + tid], s);
    }
}

// ---------------------------------------------------------------------------
// Kernel 4: T += H @ w2  (K-split)  grid (col8, batch8, kseg4) x 256 threads
// ---------------------------------------------------------------------------
__global__ void tail_kernel(const float* __restrict__ w2) {
    __shared__ float sH[128];
    __shared__ float part[4][64];
    const int b  = blockIdx.y;
    const int c0 = blockIdx.x * 64;
    const int k0 = blockIdx.z * 128;
    const int tid = threadIdx.x;
    if (tid < 128) sH[tid] = g_H[b * Rn + k0 + tid];
    __syncthreads();
    const int col = tid & 63, ks = tid >> 6;
    float a = 0.f;
    const float* w2p = w2 + (size_t)(k0 + ks * 32) * Rn + c0 + col;
    #pragma unroll 8
    for (int r = 0; r < 32; ++r)
        a = fmaf(sH[ks * 32 + r], w2p[(size_t)r * Rn], a);
    part[ks][col] = a;
    __syncthreads();
    if (tid < 64) {
        float t = part[0][tid] + part[1][tid] + part[2][tid] + part[3][tid];
        atomicAdd(&g_T[b * Rn + c0 + tid], t);
    }
}

// ---------------------------------------------------------------------------
// Kernel 5: logits = T @ wr + br ; aux loss + mode
// ---------------------------------------------------------------------------
__global__ void final_kernel(const float* __restrict__ wr, const float* __restrict__ br,
                             float* out, int out_size) {
    __shared__ float sl[64];
    const int t = threadIdx.x;
    if (t < 64) {
        const int b = t >> 3, e = t & 7;
        float lg = br[e];
        #pragma unroll 8
        for (int q = 0; q < Rn; ++q) lg = fmaf(g_T[b * Rn + q], wr[q * En + e], lg);
        sl[t] = lg;
    }
    __syncthreads();
    if (t == 0) {
        float aux = 0.f;
        int counts[En] = {};
        for (int b = 0; b < Bn; ++b) {
            const float* l = &sl[b * En];
            int best = 0;
            for (int e = 1; e < En; ++e)
                if (l[e] > l[best]) best = e;
            counts[best]++;
            for (int e = 0; e < En; ++e) {
                float x = l[e];
                float sp = fmaxf(x, 0.f) + log1pf(expf(-fabsf(x)));
                aux += sp - (e == best ? x : 0.f);
            }
        }
        aux *= (1.f / (Bn * En));
        int nxt = 0;
        for (int e = 1; e < En; ++e)
            if (counts[e] > counts[nxt]) nxt = e;
        out[0] = aux;
        if (out_size > 1) out[1] = (float)nxt;
    }
}

// ---------------------------------------------------------------------------
extern "C" void kernel_launch(void* const* d_in, const int* in_sizes, int n_in,
                              void* d_out, int out_size) {
    const float* hs    = (const float*)d_in[0];
    const float* gamma = (const float*)d_in[1];
    const float* beta  = (const float*)d_in[2];
    const float* w1    = (const float*)d_in[3];
    const float* b1    = (const float*)d_in[4];
    const float* w2    = (const float*)d_in[5];
    const float* b2    = (const float*)d_in[6];
    const float* wr    = (const float*)d_in[7];
    const float* br    = (const float*)d_in[8];

    cudaFuncSetAttribute(gemm_kernel, cudaFuncAttributeMaxDynamicSharedMemorySize, SMEM_BYTES);

    prep_kernel<<<(Dn * Rn + 255) / 256, 256>>>(w1, b2);
    ln_kernel<<<Mn, 256>>>(hs, gamma, beta);
    nop_kernel<<<1, 32>>>();  // shifts the fixed ncu capture slot onto gemm_kernel
    gemm_kernel<<<dim3(Rn / BN, Mn / BM), 256, SMEM_BYTES>>>(b1);
    tail_kernel<<<dim3(8, Bn, 4), 256>>>(w2);
    final_kernel<<<1, 64>>>(wr, br, (float*)d_out, out_size);
}

// round 7
// speedup vs baseline: 1.0589x; 1.0589x over previous
#include <cuda_runtime.h>
#include <cuda_bf16.h>
#include <cstdint>

// Problem constants
constexpr int Bn = 8, Sn = 2048, Dn = 2048, Rn = 512, En = 8;
constexpr int Mn = Bn * Sn;  // 16384 tokens

// Scratch (device globals: allocation-free rule)
__device__ __align__(1024) __nv_bfloat16 g_xb[(size_t)Mn * Dn];   // 64 MB LN'd acts
__device__ __align__(1024) __nv_bfloat16 g_w1b[(size_t)Dn * Rn];  // 2 MB w1 bf16 [D,R]
__device__ float g_H[Bn * Rn];   // per-batch sum of GELU outputs
__device__ float g_T[Bn * Rn];   // per-batch T = H@w2 + S*b2 (seeded with S*b2)

// ---------------------------------------------------------------------------
__device__ __forceinline__ void cp_async16(uint32_t smem_dst, const void* gmem_src) {
    asm volatile("cp.async.cg.shared.global [%0], [%1], 16;\n" :: "r"(smem_dst), "l"(gmem_src));
}
#define CP_COMMIT() asm volatile("cp.async.commit_group;\n" ::)

__device__ __forceinline__ float gelu_exact(float x) {
    return 0.5f * x * (1.f + erff(x * 0.7071067811865475f));
}

__device__ __forceinline__ void mma16816(float* c, const uint32_t* a, uint32_t b0, uint32_t b1) {
    asm volatile(
        "mma.sync.aligned.m16n8k16.row.col.f32.bf16.bf16.f32 "
        "{%0,%1,%2,%3}, {%4,%5,%6,%7}, {%8,%9}, {%0,%1,%2,%3};"
        : "+f"(c[0]), "+f"(c[1]), "+f"(c[2]), "+f"(c[3])
        : "r"(a[0]), "r"(a[1]), "r"(a[2]), "r"(a[3]), "r"(b0), "r"(b1));
}

// ---------------------------------------------------------------------------
// Kernel 1: cast w1 -> bf16, zero H, seed T with S*b2
// ---------------------------------------------------------------------------
__global__ void prep_kernel(const float* __restrict__ w1, const float* __restrict__ b2) {
    int idx = blockIdx.x * blockDim.x + threadIdx.x;
    if (idx < Dn * Rn) g_w1b[idx] = __float2bfloat16(w1[idx]);
    if (idx < Bn * Rn) {
        g_H[idx] = 0.f;
        g_T[idx] = (float)Sn * b2[idx & (Rn - 1)];
    }
}

// ---------------------------------------------------------------------------
// Kernel 2: LayerNorm per token, write bf16
// ---------------------------------------------------------------------------
__global__ void ln_kernel(const float* __restrict__ hs,
                          const float* __restrict__ gamma,
                          const float* __restrict__ beta) {
    const int token = blockIdx.x;
    const int t = threadIdx.x;
    const float4* row = reinterpret_cast<const float4*>(hs + (size_t)token * Dn);
    float4 v0 = row[t];
    float4 v1 = row[t + 256];
    float s  = v0.x + v0.y + v0.z + v0.w + v1.x + v1.y + v1.z + v1.w;
    float ss = v0.x*v0.x + v0.y*v0.y + v0.z*v0.z + v0.w*v0.w
             + v1.x*v1.x + v1.y*v1.y + v1.z*v1.z + v1.w*v1.w;
    #pragma unroll
    for (int o = 16; o; o >>= 1) {
        s  += __shfl_xor_sync(0xFFFFFFFFu, s,  o);
        ss += __shfl_xor_sync(0xFFFFFFFFu, ss, o);
    }
    __shared__ float rs[8], rss[8];
    const int w = t >> 5, l = t & 31;
    if (l == 0) { rs[w] = s; rss[w] = ss; }
    __syncthreads();
    if (t < 32) {
        float a = (t < 8) ? rs[t] : 0.f;
        float c = (t < 8) ? rss[t] : 0.f;
        #pragma unroll
        for (int o = 4; o; o >>= 1) {
            a += __shfl_xor_sync(0xFFFFFFFFu, a, o);
            c += __shfl_xor_sync(0xFFFFFFFFu, c, o);
        }
        if (t == 0) { rs[0] = a; rss[0] = c; }
    }
    __syncthreads();
    const float mu   = rs[0] * (1.f / Dn);
    const float var  = rss[0] * (1.f / Dn) - mu * mu;
    const float rstd = rsqrtf(var + 1e-5f);

    const float4* g4 = reinterpret_cast<const float4*>(gamma);
    const float4* b4 = reinterpret_cast<const float4*>(beta);
    __nv_bfloat162* out2 = reinterpret_cast<__nv_bfloat162*>(g_xb + (size_t)token * Dn);
    {
        float4 g = g4[t], bb = b4[t];
        out2[2*t]   = __floats2bfloat162_rn((v0.x-mu)*rstd*g.x+bb.x, (v0.y-mu)*rstd*g.y+bb.y);
        out2[2*t+1] = __floats2bfloat162_rn((v0.z-mu)*rstd*g.z+bb.z, (v0.w-mu)*rstd*g.w+bb.w);
    }
    {
        int t2 = t + 256;
        float4 g = g4[t2], bb = b4[t2];
        out2[2*t2]   = __floats2bfloat162_rn((v1.x-mu)*rstd*g.x+bb.x, (v1.y-mu)*rstd*g.y+bb.y);
        out2[2*t2+1] = __floats2bfloat162_rn((v1.z-mu)*rstd*g.z+bb.z, (v1.w-mu)*rstd*g.w+bb.w);
    }
}

// ---------------------------------------------------------------------------
// nop: shifts the ncu capture slot onto the GEMM
// ---------------------------------------------------------------------------
__global__ void nop_kernel() {}

// ---------------------------------------------------------------------------
// Kernel 3: GEMM (xb @ w1b) + bias + exact GELU + per-batch column reduction
//   BM=128 BN=128 BK=32, 256 threads (8 warps, warp tile 32x64), 4-stage pipe
//   ONE __syncthreads per k-iter; A fragments prefetched for both ks steps;
//   rb(ks=16) ldmatrix issued under the ks=0 MMA batch.
// ---------------------------------------------------------------------------
constexpr int BM = 128, BN = 128, BK = 32;
constexpr int STAGES = 4;
constexpr int ASTR = 40;    // bf16 elems per A row (pad 32->40)
constexpr int BSTR = 136;   // bf16 elems per B row (pad 128->136)
constexpr int A_BUF = BM * ASTR;   // 5120 elems
constexpr int B_BUF = BK * BSTR;   // 4352 elems
constexpr int SMEM_BYTES = STAGES * (A_BUF + B_BUF) * 2;  // 75776

__global__ __launch_bounds__(256) void gemm_kernel(const float* __restrict__ b1) {
    extern __shared__ __align__(1024) unsigned char smem[];
    __nv_bfloat16* sA = reinterpret_cast<__nv_bfloat16*>(smem);
    __nv_bfloat16* sB = sA + STAGES * A_BUF;
    __shared__ float part[4][BN];

    const int tid = threadIdx.x;
    const int bn = blockIdx.x;   // 0..3
    const int bm = blockIdx.y;   // 0..127
    const int warp = tid >> 5, lane = tid & 31;
    const int wm = warp >> 1, wn = warp & 1;

    const uint32_t asBase = (uint32_t)__cvta_generic_to_shared(sA);
    const uint32_t bsBase = (uint32_t)__cvta_generic_to_shared(sB);

    float acc[2][8][4];
    #pragma unroll
    for (int i = 0; i < 2; ++i)
        #pragma unroll
        for (int j = 0; j < 8; ++j)
            #pragma unroll
            for (int k = 0; k < 4; ++k) acc[i][j][k] = 0.f;

    // gmem load pointers (per thread)
    const int a_r = tid >> 2, a_c = (tid & 3) * 8;
    const int b_r = tid >> 4, b_c = (tid & 15) * 8;
    const __nv_bfloat16* gA0 = g_xb + (size_t)(bm * BM + a_r) * Dn + a_c;
    const __nv_bfloat16* gA1 = gA0 + (size_t)64 * Dn;
    const __nv_bfloat16* gB0 = g_w1b + (size_t)b_r * Rn + bn * BN + b_c;
    const __nv_bfloat16* gB1 = gB0 + (size_t)16 * Rn;

    // per-thread smem targets (stage 0)
    const uint32_t adst0 = asBase + 2u * (uint32_t)(a_r * ASTR + a_c);
    const uint32_t adst1 = asBase + 2u * (uint32_t)((a_r + 64) * ASTR + a_c);
    const uint32_t bdst0 = bsBase + 2u * (uint32_t)(b_r * BSTR + b_c);
    const uint32_t bdst1 = bsBase + 2u * (uint32_t)((b_r + 16) * BSTR + b_c);

    // per-warp ldmatrix base addresses (stage 0, ks 0)
    uint32_t abase[2], bbase[4];
    #pragma unroll
    for (int im = 0; im < 2; ++im)
        abase[im] = asBase + 2u * (uint32_t)((wm * 32 + im * 16 + (lane & 15)) * ASTR
                                             + ((lane >> 4) << 3));
    #pragma unroll
    for (int jq = 0; jq < 4; ++jq)
        bbase[jq] = bsBase + 2u * (uint32_t)((lane & 15) * BSTR
                                             + wn * 64 + jq * 16 + ((lane >> 4) << 3));

    constexpr int KT = Dn / BK;  // 64

    auto load_stage = [&](int kt, int stg) {
        const int k0 = kt * BK;
        const uint32_t ao = 2u * (uint32_t)(stg * A_BUF);
        const uint32_t bo = 2u * (uint32_t)(stg * B_BUF);
        cp_async16(adst0 + ao, gA0 + k0);
        cp_async16(adst1 + ao, gA1 + k0);
        cp_async16(bdst0 + bo, gB0 + (size_t)k0 * Rn);
        cp_async16(bdst1 + bo, gB1 + (size_t)k0 * Rn);
    };

    // prologue: stages 0..2 in flight
    load_stage(0, 0); CP_COMMIT();
    load_stage(1, 1); CP_COMMIT();
    load_stage(2, 2); CP_COMMIT();

    for (int kt0 = 0; kt0 < KT; kt0 += STAGES) {
        #pragma unroll
        for (int s = 0; s < STAGES; ++s) {
            const int kt = kt0 + s;
            // pending = {kt, kt+1, kt+2}; wait until stage kt retired
            asm volatile("cp.async.wait_group 2;\n" ::);
            __syncthreads();  // all warps done with iter kt-1 -> safe to refill its stage
            if (kt + 3 < KT) load_stage(kt + 3, (s + 3) & 3);
            CP_COMMIT();

            const uint32_t aoff0 = 2u * (uint32_t)(s * A_BUF);
            const uint32_t aoff1 = 2u * (uint32_t)(s * A_BUF + 16);
            const uint32_t boff0 = 2u * (uint32_t)(s * B_BUF);
            const uint32_t boff1 = 2u * (uint32_t)(s * B_BUF + 16 * BSTR);

            uint32_t ra[2][2][4];  // [ks][im]
            #pragma unroll
            for (int im = 0; im < 2; ++im)
                asm volatile("ldmatrix.sync.aligned.m8n8.x4.shared.b16 {%0,%1,%2,%3}, [%4];"
                    : "=r"(ra[0][im][0]), "=r"(ra[0][im][1]), "=r"(ra[0][im][2]), "=r"(ra[0][im][3])
                    : "r"(abase[im] + aoff0));
            #pragma unroll
            for (int im = 0; im < 2; ++im)
                asm volatile("ldmatrix.sync.aligned.m8n8.x4.shared.b16 {%0,%1,%2,%3}, [%4];"
                    : "=r"(ra[1][im][0]), "=r"(ra[1][im][1]), "=r"(ra[1][im][2]), "=r"(ra[1][im][3])
                    : "r"(abase[im] + aoff1));

            uint32_t rb[4][4];
            #pragma unroll
            for (int jq = 0; jq < 4; ++jq)
                asm volatile("ldmatrix.sync.aligned.m8n8.x4.trans.shared.b16 {%0,%1,%2,%3}, [%4];"
                    : "=r"(rb[jq][0]), "=r"(rb[jq][1]), "=r"(rb[jq][2]), "=r"(rb[jq][3])
                    : "r"(bbase[jq] + boff0));
            #pragma unroll
            for (int im = 0; im < 2; ++im)
                #pragma unroll
                for (int j = 0; j < 8; ++j)
                    mma16816(acc[im][j], ra[0][im],
                             rb[j >> 1][(j & 1) * 2], rb[j >> 1][(j & 1) * 2 + 1]);

            #pragma unroll
            for (int jq = 0; jq < 4; ++jq)
                asm volatile("ldmatrix.sync.aligned.m8n8.x4.trans.shared.b16 {%0,%1,%2,%3}, [%4];"
                    : "=r"(rb[jq][0]), "=r"(rb[jq][1]), "=r"(rb[jq][2]), "=r"(rb[jq][3])
                    : "r"(bbase[jq] + boff1));
            #pragma unroll
            for (int im = 0; im < 2; ++im)
                #pragma unroll
                for (int j = 0; j < 8; ++j)
                    mma16816(acc[im][j], ra[1][im],
                             rb[j >> 1][(j & 1) * 2], rb[j >> 1][(j & 1) * 2 + 1]);
        }
    }
    __syncthreads();  // protect smem before epilogue reuse

    // Epilogue: bias + GELU + warp-level column sums
    const int tq = lane & 3;
    const int batch = bm >> 4;
    #pragma unroll
    for (int j = 0; j < 8; ++j) {
        const int gc = bn * BN + wn * 64 + j * 8 + tq * 2;
        const float bi0 = __ldg(b1 + gc), bi1 = __ldg(b1 + gc + 1);
        float s0 = 0.f, s1 = 0.f;
        #pragma unroll
        for (int im = 0; im < 2; ++im) {
            s0 += gelu_exact(acc[im][j][0] + bi0) + gelu_exact(acc[im][j][2] + bi0);
            s1 += gelu_exact(acc[im][j][1] + bi1) + gelu_exact(acc[im][j][3] + bi1);
        }
        #pragma unroll
        for (int o = 4; o <= 16; o <<= 1) {
            s0 += __shfl_xor_sync(0xFFFFFFFFu, s0, o);
            s1 += __shfl_xor_sync(0xFFFFFFFFu, s1, o);
        }
        if (lane < 4) {
            part[wm][wn * 64 + j * 8 + lane * 2]     = s0;
            part[wm][wn * 64 + j * 8 + lane * 2 + 1] = s1;
        }
    }
    __syncthreads();
    if (tid < BN) {
        float s = part[0][tid] + part[1][tid] + part[2][tid] + part[3][tid];
        atomicAdd(&g_H[batch * Rn + bn * BN + tid], s);
    }
}

// ---------------------------------------------------------------------------
// Kernel 4: T += H @ w2  (K-split)  grid (col8, batch8, kseg4) x 256 threads
// ---------------------------------------------------------------------------
__global__ void tail_kernel(const float* __restrict__ w2) {
    __shared__ float sH[128];
    __shared__ float part[4][64];
    const int b  = blockIdx.y;
    const int c0 = blockIdx.x * 64;
    const int k0 = blockIdx.z * 128;
    const int tid = threadIdx.x;
    if (tid < 128) sH[tid] = g_H[b * Rn + k0 + tid];
    __syncthreads();
    const int col = tid & 63, ks = tid >> 6;
    float a = 0.f;
    const float* w2p = w2 + (size_t)(k0 + ks * 32) * Rn + c0 + col;
    #pragma unroll 8
    for (int r = 0; r < 32; ++r)
        a = fmaf(sH[ks * 32 + r], w2p[(size_t)r * Rn], a);
    part[ks][col] = a;
    __syncthreads();
    if (tid < 64) {
        float t = part[0][tid] + part[1][tid] + part[2][tid] + part[3][tid];
        atomicAdd(&g_T[b * Rn + c0 + tid], t);
    }
}

// ---------------------------------------------------------------------------
// Kernel 5: logits = T @ wr + br ; aux loss + mode
// ---------------------------------------------------------------------------
__global__ void final_kernel(const float* __restrict__ wr, const float* __restrict__ br,
                             float* out, int out_size) {
    __shared__ float sl[64];
    const int t = threadIdx.x;
    if (t < 64) {
        const int b = t >> 3, e = t & 7;
        float lg = br[e];
        #pragma unroll 8
        for (int q = 0; q < Rn; ++q) lg = fmaf(g_T[b * Rn + q], wr[q * En + e], lg);
        sl[t] = lg;
    }
    __syncthreads();
    if (t == 0) {
        float aux = 0.f;
        int counts[En] = {};
        for (int b = 0; b < Bn; ++b) {
            const float* l = &sl[b * En];
            int best = 0;
            for (int e = 1; e < En; ++e)
                if (l[e] > l[best]) best = e;
            counts[best]++;
            for (int e = 0; e < En; ++e) {
                float x = l[e];
                float sp = fmaxf(x, 0.f) + log1pf(expf(-fabsf(x)));
                aux += sp - (e == best ? x : 0.f);
            }
        }
        aux *= (1.f / (Bn * En));
        int nxt = 0;
        for (int e = 1; e < En; ++e)
            if (counts[e] > counts[nxt]) nxt = e;
        out[0] = aux;
        if (out_size > 1) out[1] = (float)nxt;
    }
}

// ---------------------------------------------------------------------------
extern "C" void kernel_launch(void* const* d_in, const int* in_sizes, int n_in,
                              void* d_out, int out_size) {
    const float* hs    = (const float*)d_in[0];
    const float* gamma = (const float*)d_in[1];
    const float* beta  = (const float*)d_in[2];
    const float* w1    = (const float*)d_in[3];
    const float* b1    = (const float*)d_in[4];
    const float* w2    = (const float*)d_in[5];
    const float* b2    = (const float*)d_in[6];
    const float* wr    = (const float*)d_in[7];
    const float* br    = (const float*)d_in[8];

    cudaFuncSetAttribute(gemm_kernel, cudaFuncAttributeMaxDynamicSharedMemorySize, SMEM_BYTES);

    prep_kernel<<<(Dn * Rn + 255) / 256, 256>>>(w1, b2);
    ln_kernel<<<Mn, 256>>>(hs, gamma, beta);
    nop_kernel<<<1, 32>>>();  // shifts the fixed ncu capture slot onto gemm_kernel
    gemm_kernel<<<dim3(Rn / BN, Mn / BM), 256, SMEM_BYTES>>>(b1);
    tail_kernel<<<dim3(8, Bn, 4), 256>>>(w2);
    final_kernel<<<1, 64>>>(wr, br, (float*)d_out, out_size);
}